// round 17
// baseline (speedup 1.0000x reference)
#include <cuda_runtime.h>
#include <cuda_fp16.h>
#include <cstdint>

// relu(X[131072,256] @ W[256,256]^T + b), fp32.
// R16: R15 persistent W-resident kernel, but 8 warps (256 thr) with 64x64
// warp tiles — halves B-fragment LDSM traffic (the dominant L1 term).

#define KDIM 256
#define NDIM 256
#define BM   128
#define NTHR 256
#define GRID 148

#define SM_BIAS  0
#define SM_W     1024                    // 4 subs of [256 x 128B] = 128KB
#define SM_A     (1024 + 131072)         // 2 bufs x (2 subs of [128 x 128B]) = 64KB
#define SMEM_TOTAL (SM_A + 65536)        // 197632

__device__ __forceinline__ uint32_t smem_u32(const void* p) {
    uint32_t a;
    asm("{ .reg .u64 t; cvta.to.shared.u64 t, %1; cvt.u32.u64 %0, t; }" : "=r"(a) : "l"(p));
    return a;
}

__device__ __forceinline__ void ldm_x4(uint32_t addr, uint32_t& r0, uint32_t& r1,
                                       uint32_t& r2, uint32_t& r3) {
    asm volatile("ldmatrix.sync.aligned.m8n8.x4.shared.b16 {%0,%1,%2,%3}, [%4];"
                 : "=r"(r0), "=r"(r1), "=r"(r2), "=r"(r3) : "r"(addr));
}

__device__ __forceinline__ void mma16816(float* c, const uint32_t* a, uint32_t b0, uint32_t b1) {
    asm volatile(
        "mma.sync.aligned.m16n8k16.row.col.f32.f16.f16.f32 "
        "{%0,%1,%2,%3}, {%4,%5,%6,%7}, {%8,%9}, {%0,%1,%2,%3};"
        : "+f"(c[0]), "+f"(c[1]), "+f"(c[2]), "+f"(c[3])
        : "r"(a[0]), "r"(a[1]), "r"(a[2]), "r"(a[3]), "r"(b0), "r"(b1));
}

// convert one float4 (4 K values) -> fp16 and store swizzled into 128B-row tile
__device__ __forceinline__ void conv_store(float4 v, char* tile, int row, int c) {
    __half h0 = __float2half_rn(v.x);
    __half h1 = __float2half_rn(v.y);
    __half h2 = __float2half_rn(v.z);
    __half h3 = __float2half_rn(v.w);
    uint2 hv;
    hv.x = (uint32_t)__half_as_ushort(h0) | ((uint32_t)__half_as_ushort(h1) << 16);
    hv.y = (uint32_t)__half_as_ushort(h2) | ((uint32_t)__half_as_ushort(h3) << 16);
    uint32_t off = (uint32_t)(row * 128 + c * 8);
    uint32_t swo = off ^ ((off >> 3) & 0x70);
    *(uint2*)(tile + swo) = hv;
}

__global__ __launch_bounds__(NTHR, 1)
void gemm_hmma_kernel(const float* __restrict__ X,
                      const float* __restrict__ W,
                      const float* __restrict__ bias,
                      float* __restrict__ out,
                      int ntile) {
    extern __shared__ char sm[];
    const uint32_t smb = smem_u32(sm);
    const int tid  = threadIdx.x;
    const int wid  = tid >> 5;
    const int lane = tid & 31;
    const int bx   = blockIdx.x;

    const int wm = wid & 1;        // M half (64 rows)
    const int wn = wid >> 1;       // N quarter (64 cols)

    ((float*)(sm + SM_BIAS))[tid] = bias[tid];

    const uint32_t swx     = (uint32_t)(lane & 7) << 4;
    const int a_mrow       = wm * 64 + (lane & 7) + ((lane >> 3) & 1) * 8;
    const uint32_t a_khalf = (uint32_t)(lane >> 4) * 16;
    const int b_nrow       = wn * 64 + (lane & 7) + ((lane >> 4) ? 8 : 0);
    const uint32_t b_khalf = (uint32_t)((lane >> 3) & 1) * 16;

    const int xr = tid >> 4;       // 0..15; rows roff + xr + it*16
    const int xc = tid & 15;       // float4 slot within 64-K sub

    float acc[4][8][4];
    #pragma unroll
    for (int i = 0; i < 4; i++)
        #pragma unroll
        for (int j = 0; j < 8; j++)
            #pragma unroll
            for (int q = 0; q < 4; q++) acc[i][j][q] = 0.0f;

    // ---- prologue (once): W fp32->fp16->smem (swizzled, 4 K-subs);
    //      X(tile bx, chunk 0: K 0..127) -> A buf0.
    #pragma unroll
    for (int it = 0; it < 32; it++) {
        int id = tid + it * NTHR;          // 0..8191 : 16B fp16 units of W
        int r  = id >> 5;
        int ks = id & 31;
        int kch = ks >> 3, c = ks & 7;
        const float4* wp = (const float4*)(W + r * KDIM + ks * 8);
        float4 w0 = wp[0];
        float4 w1 = wp[1];
        __half h0 = __float2half_rn(w0.x), h1 = __float2half_rn(w0.y);
        __half h2 = __float2half_rn(w0.z), h3 = __float2half_rn(w0.w);
        __half h4 = __float2half_rn(w1.x), h5 = __float2half_rn(w1.y);
        __half h6 = __float2half_rn(w1.z), h7 = __float2half_rn(w1.w);
        uint4 hv;
        hv.x = (uint32_t)__half_as_ushort(h0) | ((uint32_t)__half_as_ushort(h1) << 16);
        hv.y = (uint32_t)__half_as_ushort(h2) | ((uint32_t)__half_as_ushort(h3) << 16);
        hv.z = (uint32_t)__half_as_ushort(h4) | ((uint32_t)__half_as_ushort(h5) << 16);
        hv.w = (uint32_t)__half_as_ushort(h6) | ((uint32_t)__half_as_ushort(h7) << 16);
        uint32_t off = (uint32_t)(r * 128 + c * 16);
        uint32_t swo = off ^ ((off >> 3) & 0x70);
        *(uint4*)(sm + SM_W + kch * 32768 + swo) = hv;
    }
    {
        const float* Xb = X + (size_t)bx * BM * KDIM;
        char* ab = sm + SM_A;
        #pragma unroll
        for (int b = 0; b < 4; b++) {          // sub = b>>1, roff = (b&1)*64
            const int sub = b >> 1, roff = (b & 1) * 64;
            #pragma unroll
            for (int it = 0; it < 4; it++) {
                int row = roff + xr + it * 16;
                float4 v = *(const float4*)(Xb + (size_t)row * KDIM + sub * 64 + xc * 4);
                conv_store(v, ab + sub * 16384, row, xc);
            }
        }
    }
    __syncthreads();

    int buf = 0;
    const float* sb = (const float*)(sm + SM_BIAS);

    for (int m = bx; m < ntile; m += GRID) {
        const float* Xb = X + (size_t)m * BM * KDIM;

        #pragma unroll
        for (int kc = 0; kc < 2; kc++) {
            const uint32_t curA = smb + SM_A + (uint32_t)(buf * 32768);
            char* nab = sm + SM_A + ((buf ^ 1) * 32768);
            const bool pre = (kc == 0) || (m + GRID < ntile);
            const float* Xn = (kc == 0) ? Xb : X + (size_t)(m + GRID) * BM * KDIM;
            const int kof0 = (kc == 0) ? 128 : 0;

            float4 xv[4];

            // LDG batch 0 (sub0, rows 0-63) up front
            if (pre) {
                #pragma unroll
                for (int it = 0; it < 4; it++)
                    xv[it] = *(const float4*)(Xn + (size_t)(xr + it * 16) * KDIM
                                              + kof0 + xc * 4);
            }

            // ---- MMA loop: 8 kk steps against resident W
            #pragma unroll
            for (int kk = 0; kk < 8; kk++) {
                const uint32_t subA = (uint32_t)((kk >> 2) * 16384);
                const uint32_t subB = (uint32_t)((kc * 2 + (kk >> 2)) * 32768);
                const uint32_t kof  = (uint32_t)((kk & 3) * 32);
                const uint32_t aB = curA + subA + (uint32_t)(a_mrow * 128)
                                    + ((kof + a_khalf) ^ swx);
                const uint32_t bB = smb + SM_W + subB + (uint32_t)(b_nrow * 128)
                                    + ((kof + b_khalf) ^ swx);

                uint32_t ah[4][4];
                ldm_x4(aB,        ah[0][0], ah[0][1], ah[0][2], ah[0][3]);
                ldm_x4(aB + 2048, ah[1][0], ah[1][1], ah[1][2], ah[1][3]);
                ldm_x4(aB + 4096, ah[2][0], ah[2][1], ah[2][2], ah[2][3]);
                ldm_x4(aB + 6144, ah[3][0], ah[3][1], ah[3][2], ah[3][3]);

                uint32_t bh[2][4];
                ldm_x4(bB, bh[0][0], bh[0][1], bh[0][2], bh[0][3]);

                #pragma unroll
                for (int ng = 0; ng < 4; ng++) {
                    const int cb = ng & 1;
                    if (ng < 3) {
                        const int nb = cb ^ 1;
                        ldm_x4(bB + (uint32_t)((ng + 1) * 2048),
                               bh[nb][0], bh[nb][1], bh[nb][2], bh[nb][3]);
                    }
                    #pragma unroll
                    for (int mb = 0; mb < 4; mb++) {
                        mma16816(acc[mb][2 * ng + 0], ah[mb], bh[cb][0], bh[cb][1]);
                        mma16816(acc[mb][2 * ng + 1], ah[mb], bh[cb][2], bh[cb][3]);
                    }
                }

                // staged X pipeline: conv batch b at kk = 2b+1, LDG batch b+1
                if (pre && (kk == 1 || kk == 3 || kk == 5)) {
                    const int b = kk >> 1;           // finished batch 0,1,2
                    const int sub = b >> 1, roff = (b & 1) * 64;
                    conv_store(xv[0], nab + sub * 16384, roff + xr,      xc);
                    conv_store(xv[1], nab + sub * 16384, roff + xr + 16, xc);
                    conv_store(xv[2], nab + sub * 16384, roff + xr + 32, xc);
                    conv_store(xv[3], nab + sub * 16384, roff + xr + 48, xc);
                    const int nb2 = b + 1;           // next batch 1,2,3
                    const int sub2 = nb2 >> 1, roff2 = (nb2 & 1) * 64;
                    #pragma unroll
                    for (int it = 0; it < 4; it++)
                        xv[it] = *(const float4*)(Xn + (size_t)(roff2 + xr + it * 16) * KDIM
                                                  + kof0 + sub2 * 64 + xc * 4);
                }
            }

            if (pre) {                      // convert final batch (sub1 rows 64-127)
                conv_store(xv[0], nab + 16384, 64 + xr,      xc);
                conv_store(xv[1], nab + 16384, 64 + xr + 16, xc);
                conv_store(xv[2], nab + 16384, 64 + xr + 32, xc);
                conv_store(xv[3], nab + 16384, 64 + xr + 48, xc);
            }
            if (kc == 0) __syncthreads();   // kc1 barrier deferred past epilogue
            buf ^= 1;
        }

        // ---- epilogue (overlaps other warps' kc1 MMA tail): bias + relu
        const int mbase = m * BM + wm * 64 + (lane >> 2);
        const int nbase = wn * 64 + (lane & 3) * 2;
        #pragma unroll
        for (int mb = 0; mb < 4; mb++) {
            #pragma unroll
            for (int nb = 0; nb < 8; nb++) {
                const int n = nbase + nb * 8;
                const float b0 = sb[n], b1 = sb[n + 1];
                const int m0 = mbase + mb * 16;
                float2 v0, v1;
                v0.x = fmaxf(acc[mb][nb][0] + b0, 0.0f);
                v0.y = fmaxf(acc[mb][nb][1] + b1, 0.0f);
                v1.x = fmaxf(acc[mb][nb][2] + b0, 0.0f);
                v1.y = fmaxf(acc[mb][nb][3] + b1, 0.0f);
                *(float2*)(out + (size_t)m0 * NDIM + n) = v0;
                *(float2*)(out + (size_t)(m0 + 8) * NDIM + n) = v1;
                acc[mb][nb][0] = 0.0f; acc[mb][nb][1] = 0.0f;
                acc[mb][nb][2] = 0.0f; acc[mb][nb][3] = 0.0f;
            }
        }

        __syncthreads();   // deferred: next-tile A buffer handoff
    }
}

extern "C" void kernel_launch(void* const* d_in, const int* in_sizes, int n_in,
                              void* d_out, int out_size) {
    const float* X    = (const float*)d_in[0];
    const float* W    = (const float*)d_in[1];
    const float* bias = (const float*)d_in[2];
    float* out = (float*)d_out;

    cudaFuncSetAttribute(gemm_hmma_kernel,
                         cudaFuncAttributeMaxDynamicSharedMemorySize, SMEM_TOTAL);

    const int ntile = in_sizes[0] / KDIM / BM;   // 1024
    gemm_hmma_kernel<<<GRID, NTHR, SMEM_TOTAL>>>(X, W, bias, out, ntile);
}